// round 12
// baseline (speedup 1.0000x reference)
#include <cuda_runtime.h>
#include <cstdint>
#include <cstddef>

// Problem constants
constexpr int B = 32;
constexpr int P = 196;
constexpr int D = 512;
constexpr int H = 8;
constexpr int U = 4;
constexpr int C = 500;

constexpr size_t KNOWN_ELEMS = (size_t)B * C * (H + 3) * D;  // 90,112,000
constexpr size_t UNK_ELEMS   = (size_t)B * (U + 3) * D;      // 114,688
// semantic_tokens tail: B*H*D = 131,072

// Scratch (allocation-free rule: __device__ globals)
__device__ float g_semtok[B * H * D];
__device__ float g_pdom[B * D];
__device__ float g_psem[B * H * D];

// ---------------------------------------------------------------------------
// Kernel 1: attention-pooled semantic tokens. One block per b, 512 threads.
// ---------------------------------------------------------------------------
__global__ __launch_bounds__(512) void k_semtok(
    const float* __restrict__ patch,   // (B,P,D)
    const float* __restrict__ query,   // (H,D)
    float* __restrict__ out_semtok)    // (B,H,D) tail section of d_out
{
    __shared__ float s_q[H * D];      // 16 KB
    __shared__ float s_sc[P * H];     // ~6.2 KB, layout [p][h]

    const int b = blockIdx.x;
    const int tid = threadIdx.x;
    const float* pb = patch + (size_t)b * P * D;

    for (int i = tid; i < H * D; i += 512) s_q[i] = query[i];
    __syncthreads();

    // scores[p][h] = dot(patch[b,p,:], query[h,:])
    for (int pair = tid; pair < P * H; pair += 512) {
        const int p = pair >> 3;
        const int h = pair & 7;
        const float4* pr = (const float4*)(pb + (size_t)p * D);
        const float4* qr = (const float4*)(s_q + h * D);
        float acc = 0.f;
        #pragma unroll 8
        for (int i = 0; i < D / 4; i++) {
            float4 a = pr[i], q = qr[i];
            acc += a.x * q.x + a.y * q.y + a.z * q.z + a.w * q.w;
        }
        s_sc[pair] = acc;
    }
    __syncthreads();

    // softmax over p per head; warp w handles head w
    const int w = tid >> 5, lane = tid & 31;
    if (w < H) {
        float m = -1e30f;
        for (int p = lane; p < P; p += 32) m = fmaxf(m, s_sc[p * H + w]);
        #pragma unroll
        for (int o = 16; o; o >>= 1) m = fmaxf(m, __shfl_xor_sync(0xffffffffu, m, o));
        float s = 0.f;
        for (int p = lane; p < P; p += 32) s += __expf(s_sc[p * H + w] - m);
        #pragma unroll
        for (int o = 16; o; o >>= 1) s += __shfl_xor_sync(0xffffffffu, s, o);
        const float inv = 1.0f / s;
        for (int p = lane; p < P; p += 32)
            s_sc[p * H + w] = __expf(s_sc[p * H + w] - m) * inv;
    }
    __syncthreads();

    // semantic_tokens[b,h,d] = sum_p w[p,h] * patch[b,p,d]; thread owns d=tid
    float acc[H];
    #pragma unroll
    for (int h = 0; h < H; h++) acc[h] = 0.f;
    const int d = tid;
    for (int p = 0; p < P; p++) {
        const float x = pb[(size_t)p * D + d];
        #pragma unroll
        for (int h = 0; h < H; h++) acc[h] += s_sc[p * H + h] * x;
    }
    #pragma unroll
    for (int h = 0; h < H; h++) {
        const float v = acc[h];
        const size_t o = ((size_t)b * H + h) * D + d;
        g_semtok[o] = v;
        out_semtok[o] = v;
    }
}

// ---------------------------------------------------------------------------
// Kernel 2: projected_domain GEMV fused with the tiny unknown_prompts output.
// One block per b, 512 threads; thread e owns output element e.
// ---------------------------------------------------------------------------
__global__ __launch_bounds__(512) void k_pdom_unknown(
    const float* __restrict__ gf,     // (B,D)
    const float* __restrict__ Wm,     // (D,D)
    const float* __restrict__ bv,     // (D,)
    const float* __restrict__ upre,   // (1,D)
    const float* __restrict__ usem,   // (U,D)
    const float* __restrict__ usuf,   // (1,D)
    float* __restrict__ out_unknown)  // (B, U+3, D)
{
    __shared__ float s_g[D];
    const int b = blockIdx.x;
    const int e = threadIdx.x;
    s_g[e] = gf[(size_t)b * D + e];
    __syncthreads();
    const float4* wr = (const float4*)(Wm + (size_t)e * D);
    const float4* gr = (const float4*)s_g;
    float acc = 0.f;
    #pragma unroll 8
    for (int i = 0; i < D / 4; i++) {
        float4 w4 = wr[i], g4 = gr[i];
        acc += w4.x * g4.x + w4.y * g4.y + w4.z * g4.z + w4.w * g4.w;
    }
    const float val = acc + bv[e];
    g_pdom[(size_t)b * D + e] = val;

    // unknown prompt for this b: [upre, dom, usem x U, usuf]
    float* o = out_unknown + (size_t)b * (U + 3) * D;
    o[e] = upre[e];
    o[D + e] = val;
    #pragma unroll
    for (int u = 0; u < U; u++)
        o[(size_t)(2 + u) * D + e] = usem[(size_t)u * D + e];
    o[(size_t)(U + 2) * D + e] = usuf[e];
}

// ---------------------------------------------------------------------------
// Kernel 3: projected_sem[b,h,e] = sum_d semtok[b,h,d]*sem_W[h,e,d] + sem_b[h,e]
// One block per (b,h); sem_W (8 MB) L2-resident across the 32 b's.
// ---------------------------------------------------------------------------
__global__ __launch_bounds__(512) void k_psem(
    const float* __restrict__ semW,   // (H,D,D)
    const float* __restrict__ semb)   // (H,D)
{
    __shared__ float s_t[D];
    const int bh = blockIdx.x;
    const int h = bh & 7;
    const int e = threadIdx.x;
    s_t[e] = g_semtok[(size_t)bh * D + e];
    __syncthreads();
    const float4* wr = (const float4*)(semW + ((size_t)h * D + e) * D);
    const float4* tr = (const float4*)s_t;
    float acc = 0.f;
    #pragma unroll 8
    for (int i = 0; i < D / 4; i++) {
        float4 w4 = wr[i], t4 = tr[i];
        acc += w4.x * t4.x + w4.y * t4.y + w4.z * t4.z + w4.w * t4.w;
    }
    g_psem[(size_t)bh * D + e] = acc + semb[(size_t)h * D + e];
}

// ---------------------------------------------------------------------------
// Kernel 4: assemble known_prompts via TMA bulk stores.
// Each block builds 2 consecutive prompts (same b: 2 | 500) in 44 KB smem,
// then issues ONE cp.async.bulk (S2G) of 45056 B. 8000 blocks x 256 thr.
// ---------------------------------------------------------------------------
constexpr int PPB        = 2;                    // prompts per block
constexpr int ROW_F4     = D / 4;                // 128
constexpr int PROMPT_ROWS = H + 3;               // 11
constexpr int PROMPT_F4  = PROMPT_ROWS * ROW_F4; // 1408
constexpr int BLK_F4     = PPB * PROMPT_F4;      // 2816
constexpr unsigned BLK_BYTES = BLK_F4 * 16u;     // 45056 (<48KB static smem)

__global__ __launch_bounds__(256) void k_known(
    const float* __restrict__ pre,    // (C,1,D)
    const float* __restrict__ suf,    // (C,1,D)
    float* __restrict__ out)
{
    __shared__ __align__(128) float4 s_buf[BLK_F4];

    const int pair0 = blockIdx.x * PPB;   // global prompt index bc
    const int b = pair0 / C;              // PPB divides C, so b uniform in block
    const int c0 = pair0 - b * C;
    const int t = threadIdx.x;

    const float4* f_pre = (const float4*)pre;
    const float4* f_suf = (const float4*)suf;
    const float4* f_dom = (const float4*)(g_pdom + (size_t)b * D);
    const float4* f_sem = (const float4*)(g_psem + (size_t)b * H * D);

    #pragma unroll
    for (int k = 0; k < BLK_F4 / 256; k++) {   // 11 iterations
        const int idx = t + k * 256;
        const int v   = idx & (ROW_F4 - 1);    // float4 lane in row
        const int row = idx >> 7;              // 0..21 (warp-uniform)
        const int j   = row / PROMPT_ROWS;     // which prompt
        const int r   = row - j * PROMPT_ROWS; // row within prompt
        const int c   = c0 + j;
        float4 val;
        if (r == 0)                 val = f_pre[c * ROW_F4 + v];
        else if (r == 1)            val = f_dom[v];
        else if (r == PROMPT_ROWS - 1) val = f_suf[c * ROW_F4 + v];
        else                        val = f_sem[(r - 2) * ROW_F4 + v];
        s_buf[idx] = val;
    }
    __syncthreads();

    if (t == 0) {
        asm volatile("fence.proxy.async.shared::cta;" ::: "memory");
        uint32_t saddr = (uint32_t)__cvta_generic_to_shared(s_buf);
        float* gdst = out + (size_t)pair0 * PROMPT_ROWS * D;
        unsigned nbytes = BLK_BYTES;
        asm volatile("cp.async.bulk.global.shared::cta.bulk_group [%0], [%1], %2;"
                     :: "l"(gdst), "r"(saddr), "r"(nbytes) : "memory");
        asm volatile("cp.async.bulk.commit_group;" ::: "memory");
        asm volatile("cp.async.bulk.wait_group 0;" ::: "memory");
    }
}

// ---------------------------------------------------------------------------
extern "C" void kernel_launch(void* const* d_in, const int* in_sizes, int n_in,
                              void* d_out, int out_size)
{
    const float* patch  = (const float*)d_in[0];   // (B,P,D)
    const float* gfeat  = (const float*)d_in[1];   // (B,D)
    const float* query  = (const float*)d_in[2];   // (H,D)
    const float* dom_W  = (const float*)d_in[3];   // (D,D)
    const float* dom_b  = (const float*)d_in[4];   // (D,)
    const float* sem_W  = (const float*)d_in[5];   // (H,D,D)
    const float* sem_b  = (const float*)d_in[6];   // (H,D)
    const float* usem   = (const float*)d_in[7];   // (U,D)
    const float* kpre   = (const float*)d_in[8];   // (C,1,D)
    const float* ksuf   = (const float*)d_in[9];   // (C,1,D)
    const float* upre   = (const float*)d_in[10];  // (1,D)
    const float* usuf   = (const float*)d_in[11];  // (1,D)

    float* out = (float*)d_out;
    float* out_unknown = out + KNOWN_ELEMS;
    float* out_semtok  = out + KNOWN_ELEMS + UNK_ELEMS;

    k_semtok<<<B, 512>>>(patch, query, out_semtok);
    k_pdom_unknown<<<B, 512>>>(gfeat, dom_W, dom_b, upre, usem, usuf, out_unknown);
    k_psem<<<B * H, 512>>>(sem_W, sem_b);
    k_known<<<(B * C) / PPB, 256>>>(kpre, ksuf, out);
}

// round 14
// speedup vs baseline: 1.6864x; 1.6864x over previous
#include <cuda_runtime.h>
#include <cstdint>
#include <cstddef>

constexpr int B = 32;
constexpr int P = 196;
constexpr int D = 512;
constexpr int H = 8;
constexpr int U = 4;
constexpr int C = 500;

constexpr size_t KNOWN_ELEMS = (size_t)B * C * (H + 3) * D;  // 90,112,000
constexpr size_t UNK_ELEMS   = (size_t)B * (U + 3) * D;      // 114,688

// __device__ scratch (allocation-free rule)
__device__ float g_scores[B * P * H];
__device__ float g_semtok[B * H * D];
__device__ float g_pdom[B * D];
__device__ float g_psem[B * H * D];

// ---------------------------------------------------------------------------
// K1: scores[b,p,h] = dot(patch[b,p,:], query[h,:]).
// Warp handles 2 rows; full-chip grid (392 blocks) so patch's 25.7MB DRAM
// first-read is latency-hidden.
// ---------------------------------------------------------------------------
__global__ __launch_bounds__(256) void k_scores(
    const float* __restrict__ patch,   // (B,P,D)
    const float* __restrict__ query)   // (H,D)
{
    __shared__ float4 s_q[H * (D / 4)];   // 16 KB
    const int tid = threadIdx.x, wid = tid >> 5, lane = tid & 31;

    for (int i = tid; i < H * (D / 4); i += 256)
        s_q[i] = ((const float4*)query)[i];
    __syncthreads();

    const int row0 = (blockIdx.x * 8 + wid) * 2;     // 2 rows per warp
    const float4* p0 = (const float4*)(patch + (size_t)row0 * D);
    const float4* p1 = (const float4*)(patch + (size_t)(row0 + 1) * D);

    float4 ra[4], rb[4];
    #pragma unroll
    for (int k = 0; k < 4; k++) { ra[k] = p0[lane + 32 * k]; rb[k] = p1[lane + 32 * k]; }

    float acc[16];
    #pragma unroll
    for (int j = 0; j < 16; j++) acc[j] = 0.f;

    #pragma unroll
    for (int h = 0; h < 8; h++) {
        #pragma unroll
        for (int k = 0; k < 4; k++) {
            const float4 q = s_q[h * 128 + lane + 32 * k];
            acc[h]     += ra[k].x * q.x + ra[k].y * q.y + ra[k].z * q.z + ra[k].w * q.w;
            acc[8 + h] += rb[k].x * q.x + rb[k].y * q.y + rb[k].z * q.z + rb[k].w * q.w;
        }
    }
    #pragma unroll
    for (int j = 0; j < 16; j++) {
        float v = acc[j];
        #pragma unroll
        for (int o = 16; o; o >>= 1) v += __shfl_xor_sync(0xffffffffu, v, o);
        acc[j] = v;
    }
    if (lane == 0) {
        #pragma unroll
        for (int j = 0; j < 16; j++) {
            const int r = j >> 3, h = j & 7;
            const int row = row0 + r;
            const int b = row / P, p = row - b * P;
            g_scores[(size_t)b * (P * H) + p * H + h] = acc[j];
        }
    }
}

// ---------------------------------------------------------------------------
// K2: softmax over p (per b,h) + weighted pooling. Block per (b, d-half).
// Patch is L2-resident after K1.
// ---------------------------------------------------------------------------
__global__ __launch_bounds__(256) void k_softmax_pool(
    const float* __restrict__ patch,
    float* __restrict__ out_semtok)
{
    __shared__ __align__(16) float s_w[P * H];   // 6.3 KB, layout [p][h]
    const int b  = blockIdx.x >> 1;
    const int dh = blockIdx.x & 1;
    const int tid = threadIdx.x;

    for (int i = tid; i < P * H; i += 256) s_w[i] = g_scores[(size_t)b * (P * H) + i];
    __syncthreads();

    const int w = tid >> 5, lane = tid & 31;     // warp w = head w
    {
        float m = -1e30f;
        for (int p = lane; p < P; p += 32) m = fmaxf(m, s_w[p * H + w]);
        #pragma unroll
        for (int o = 16; o; o >>= 1) m = fmaxf(m, __shfl_xor_sync(0xffffffffu, m, o));
        float s = 0.f;
        for (int p = lane; p < P; p += 32) s += __expf(s_w[p * H + w] - m);
        #pragma unroll
        for (int o = 16; o; o >>= 1) s += __shfl_xor_sync(0xffffffffu, s, o);
        const float inv = 1.0f / s;
        for (int p = lane; p < P; p += 32)
            s_w[p * H + w] = __expf(s_w[p * H + w] - m) * inv;
    }
    __syncthreads();

    const int d = dh * 256 + tid;
    const float* pb = patch + (size_t)b * P * D + d;
    float acc[8];
    #pragma unroll
    for (int h = 0; h < 8; h++) acc[h] = 0.f;

    #pragma unroll 4
    for (int p = 0; p < P; p++) {
        const float x = pb[(size_t)p * D];
        const float4 w0 = *(const float4*)&s_w[p * H];
        const float4 w1 = *(const float4*)&s_w[p * H + 4];
        acc[0] += w0.x * x; acc[1] += w0.y * x; acc[2] += w0.z * x; acc[3] += w0.w * x;
        acc[4] += w1.x * x; acc[5] += w1.y * x; acc[6] += w1.z * x; acc[7] += w1.w * x;
    }
    #pragma unroll
    for (int h = 0; h < 8; h++) {
        const size_t o = ((size_t)b * H + h) * D + d;
        g_semtok[o] = acc[h];
        out_semtok[o] = acc[h];
    }
}

// ---------------------------------------------------------------------------
// K3: projected_sem[b,h,e] = sum_d semtok[b,h,d]*sem_W[h,e,d] + sem_b[h,e].
// Grid 64 = (h:8, b-half:2, e-tile:4). 16 b's staged in padded smem; each
// thread owns one e and 4 b's -> every sem_W float4 reused 4x. Traffic 16MB.
// ---------------------------------------------------------------------------
constexpr int PS_STRIDE = 516;  // padded row stride (floats), kills bank conflicts

__global__ __launch_bounds__(512) void k_psem(
    const float* __restrict__ semW,   // (H,D,D)
    const float* __restrict__ semb)   // (H,D)
{
    __shared__ float s_t[16 * PS_STRIDE];   // 33 KB
    const int blk = blockIdx.x;
    const int h  = blk >> 3;
    const int bh = (blk >> 2) & 1;
    const int et = blk & 3;
    const int tid = threadIdx.x;
    const int b0 = bh * 16;

    for (int i = tid; i < 16 * (D / 4); i += 512) {  // 2048 float4
        const int bb = i >> 7, col = i & 127;
        const float4 v = *(const float4*)&g_semtok[((size_t)(b0 + bb) * H + h) * D + col * 4];
        *(float4*)&s_t[bb * PS_STRIDE + col * 4] = v;
    }
    __syncthreads();

    const int e  = et * 128 + (tid >> 2);
    const int bq = tid & 3;
    const float4* wrow = (const float4*)(semW + ((size_t)h * D + e) * D);
    const float* t0 = &s_t[(bq * 4 + 0) * PS_STRIDE];
    const float* t1 = &s_t[(bq * 4 + 1) * PS_STRIDE];
    const float* t2 = &s_t[(bq * 4 + 2) * PS_STRIDE];
    const float* t3 = &s_t[(bq * 4 + 3) * PS_STRIDE];

    float a0 = 0.f, a1 = 0.f, a2 = 0.f, a3 = 0.f;
    #pragma unroll 16
    for (int i = 0; i < 128; i++) {
        const float4 w4 = wrow[i];
        const float4 x0 = *(const float4*)&t0[i * 4];
        const float4 x1 = *(const float4*)&t1[i * 4];
        const float4 x2 = *(const float4*)&t2[i * 4];
        const float4 x3 = *(const float4*)&t3[i * 4];
        a0 += w4.x * x0.x + w4.y * x0.y + w4.z * x0.z + w4.w * x0.w;
        a1 += w4.x * x1.x + w4.y * x1.y + w4.z * x1.z + w4.w * x1.w;
        a2 += w4.x * x2.x + w4.y * x2.y + w4.z * x2.z + w4.w * x2.w;
        a3 += w4.x * x3.x + w4.y * x3.y + w4.z * x3.z + w4.w * x3.w;
    }
    const float bias = semb[(size_t)h * D + e];
    const float r[4] = {a0 + bias, a1 + bias, a2 + bias, a3 + bias};
    #pragma unroll
    for (int j = 0; j < 4; j++)
        g_psem[((size_t)(b0 + bq * 4 + j) * H + h) * D + e] = r[j];
}

// ---------------------------------------------------------------------------
// K4: projected_domain (same tiling, no h) fused with unknown_prompts.
// Grid 8 = (b-half:2, e-tile:4); each block also writes broadcast rows for 4 b.
// ---------------------------------------------------------------------------
__global__ __launch_bounds__(512) void k_pdom_unknown(
    const float* __restrict__ gf,     // (B,D)
    const float* __restrict__ Wm,     // (D,D)
    const float* __restrict__ bv,     // (D,)
    const float* __restrict__ upre,   // (1,D)
    const float* __restrict__ usem,   // (U,D)
    const float* __restrict__ usuf,   // (1,D)
    float* __restrict__ out_unknown)  // (B, U+3, D)
{
    __shared__ float s_g[16 * PS_STRIDE];
    const int blk = blockIdx.x;       // 0..7
    const int bh = blk >> 2;
    const int et = blk & 3;
    const int tid = threadIdx.x;
    const int b0 = bh * 16;

    for (int i = tid; i < 16 * (D / 4); i += 512) {
        const int bb = i >> 7, col = i & 127;
        const float4 v = *(const float4*)&gf[(size_t)(b0 + bb) * D + col * 4];
        *(float4*)&s_g[bb * PS_STRIDE + col * 4] = v;
    }
    __syncthreads();

    const int e  = et * 128 + (tid >> 2);
    const int bq = tid & 3;
    const float4* wrow = (const float4*)(Wm + (size_t)e * D);
    const float* t0 = &s_g[(bq * 4 + 0) * PS_STRIDE];
    const float* t1 = &s_g[(bq * 4 + 1) * PS_STRIDE];
    const float* t2 = &s_g[(bq * 4 + 2) * PS_STRIDE];
    const float* t3 = &s_g[(bq * 4 + 3) * PS_STRIDE];

    float a0 = 0.f, a1 = 0.f, a2 = 0.f, a3 = 0.f;
    #pragma unroll 16
    for (int i = 0; i < 128; i++) {
        const float4 w4 = wrow[i];
        const float4 x0 = *(const float4*)&t0[i * 4];
        const float4 x1 = *(const float4*)&t1[i * 4];
        const float4 x2 = *(const float4*)&t2[i * 4];
        const float4 x3 = *(const float4*)&t3[i * 4];
        a0 += w4.x * x0.x + w4.y * x0.y + w4.z * x0.z + w4.w * x0.w;
        a1 += w4.x * x1.x + w4.y * x1.y + w4.z * x1.z + w4.w * x1.w;
        a2 += w4.x * x2.x + w4.y * x2.y + w4.z * x2.z + w4.w * x2.w;
        a3 += w4.x * x3.x + w4.y * x3.y + w4.z * x3.z + w4.w * x3.w;
    }
    const float bias = bv[e];
    #pragma unroll
    for (int j = 0; j < 4; j++) {
        const int b = b0 + bq * 4 + j;
        const float val = (j == 0 ? a0 : j == 1 ? a1 : j == 2 ? a2 : a3) + bias;
        g_pdom[(size_t)b * D + e] = val;
        out_unknown[(size_t)b * ((U + 3) * D) + D + e] = val;   // row 1 = dom
    }

    // broadcast rows for 4 b's per block: row0=upre, rows2..5=usem, row6=usuf
    for (int i = tid; i < 4 * 6 * D; i += 512) {
        const int bb = i / (6 * D);
        const int rem = i - bb * (6 * D);
        const int rr = rem >> 9;          // 0..5
        const int dd = rem & (D - 1);
        int brow; float v;
        if (rr == 0)      { brow = 0;       v = upre[dd]; }
        else if (rr <= 4) { brow = 1 + rr;  v = usem[(size_t)(rr - 1) * D + dd]; }
        else              { brow = U + 2;   v = usuf[dd]; }
        out_unknown[(size_t)(blk * 4 + bb) * ((U + 3) * D) + (size_t)brow * D + dd] = v;
    }
}

// ---------------------------------------------------------------------------
// K5: known_prompts via smem staging + one 45KB cp.async.bulk S2G per block.
// MEASURED: 54.7us @ 5534 GB/s (69.8% DRAM). Unchanged.
// ---------------------------------------------------------------------------
constexpr int PPB        = 2;
constexpr int ROW_F4     = D / 4;                // 128
constexpr int PROMPT_ROWS = H + 3;               // 11
constexpr int PROMPT_F4  = PROMPT_ROWS * ROW_F4; // 1408
constexpr int BLK_F4     = PPB * PROMPT_F4;      // 2816
constexpr unsigned BLK_BYTES = BLK_F4 * 16u;     // 45056

__global__ __launch_bounds__(256) void k_known(
    const float* __restrict__ pre,    // (C,1,D)
    const float* __restrict__ suf,    // (C,1,D)
    float* __restrict__ out)
{
    __shared__ __align__(128) float4 s_buf[BLK_F4];

    const int pair0 = blockIdx.x * PPB;
    const int b = pair0 / C;
    const int c0 = pair0 - b * C;
    const int t = threadIdx.x;

    const float4* f_pre = (const float4*)pre;
    const float4* f_suf = (const float4*)suf;
    const float4* f_dom = (const float4*)(g_pdom + (size_t)b * D);
    const float4* f_sem = (const float4*)(g_psem + (size_t)b * H * D);

    #pragma unroll
    for (int k = 0; k < BLK_F4 / 256; k++) {
        const int idx = t + k * 256;
        const int v   = idx & (ROW_F4 - 1);
        const int row = idx >> 7;
        const int j   = row / PROMPT_ROWS;
        const int r   = row - j * PROMPT_ROWS;
        const int c   = c0 + j;
        float4 val;
        if (r == 0)                    val = f_pre[c * ROW_F4 + v];
        else if (r == 1)               val = f_dom[v];
        else if (r == PROMPT_ROWS - 1) val = f_suf[c * ROW_F4 + v];
        else                           val = f_sem[(r - 2) * ROW_F4 + v];
        s_buf[idx] = val;
    }
    __syncthreads();

    if (t == 0) {
        asm volatile("fence.proxy.async.shared::cta;" ::: "memory");
        uint32_t saddr = (uint32_t)__cvta_generic_to_shared(s_buf);
        float* gdst = out + (size_t)pair0 * PROMPT_ROWS * D;
        unsigned nbytes = BLK_BYTES;
        asm volatile("cp.async.bulk.global.shared::cta.bulk_group [%0], [%1], %2;"
                     :: "l"(gdst), "r"(saddr), "r"(nbytes) : "memory");
        asm volatile("cp.async.bulk.commit_group;" ::: "memory");
        asm volatile("cp.async.bulk.wait_group 0;" ::: "memory");
    }
}

// ---------------------------------------------------------------------------
extern "C" void kernel_launch(void* const* d_in, const int* in_sizes, int n_in,
                              void* d_out, int out_size)
{
    const float* patch  = (const float*)d_in[0];
    const float* gfeat  = (const float*)d_in[1];
    const float* query  = (const float*)d_in[2];
    const float* dom_W  = (const float*)d_in[3];
    const float* dom_b  = (const float*)d_in[4];
    const float* sem_W  = (const float*)d_in[5];
    const float* sem_b  = (const float*)d_in[6];
    const float* usem   = (const float*)d_in[7];
    const float* kpre   = (const float*)d_in[8];
    const float* ksuf   = (const float*)d_in[9];
    const float* upre   = (const float*)d_in[10];
    const float* usuf   = (const float*)d_in[11];

    float* out = (float*)d_out;
    float* out_unknown = out + KNOWN_ELEMS;
    float* out_semtok  = out + KNOWN_ELEMS + UNK_ELEMS;

    k_scores<<<(B * P) / 16, 256>>>(patch, query);
    k_softmax_pool<<<B * 2, 256>>>(patch, out_semtok);
    k_psem<<<64, 512>>>(sem_W, sem_b);
    k_pdom_unknown<<<8, 512>>>(gfeat, dom_W, dom_b, upre, usem, usuf, out_unknown);
    k_known<<<(B * C) / PPB, 256>>>(kpre, ksuf, out);
}

// round 15
// speedup vs baseline: 2.2330x; 1.3241x over previous
#include <cuda_runtime.h>
#include <cstdint>
#include <cstddef>

constexpr int B = 32;
constexpr int P = 196;
constexpr int D = 512;
constexpr int H = 8;
constexpr int U = 4;
constexpr int C = 500;

constexpr size_t KNOWN_ELEMS = (size_t)B * C * (H + 3) * D;  // 90,112,000
constexpr size_t UNK_ELEMS   = (size_t)B * (U + 3) * D;      // 114,688

// __device__ scratch (allocation-free rule)
__device__ float g_scores[B * P * H];
__device__ float g_semtok[B * H * D];
__device__ float g_pdom[B * D];
__device__ float g_psem[B * H * D];

// ---------------------------------------------------------------------------
// K1: scores[b,p,h] = dot(patch[b,p,:], query[h,:]). 392 blocks (full chip);
// warp handles 2 patch rows. Unchanged from R14 (part of the win).
// ---------------------------------------------------------------------------
__global__ __launch_bounds__(256) void k_scores(
    const float* __restrict__ patch,   // (B,P,D)
    const float* __restrict__ query)   // (H,D)
{
    __shared__ float4 s_q[H * (D / 4)];   // 16 KB
    const int tid = threadIdx.x, wid = tid >> 5, lane = tid & 31;

    for (int i = tid; i < H * (D / 4); i += 256)
        s_q[i] = ((const float4*)query)[i];
    __syncthreads();

    const int row0 = (blockIdx.x * 8 + wid) * 2;     // 2 rows per warp
    const float4* p0 = (const float4*)(patch + (size_t)row0 * D);
    const float4* p1 = (const float4*)(patch + (size_t)(row0 + 1) * D);

    float4 ra[4], rb[4];
    #pragma unroll
    for (int k = 0; k < 4; k++) { ra[k] = p0[lane + 32 * k]; rb[k] = p1[lane + 32 * k]; }

    float acc[16];
    #pragma unroll
    for (int j = 0; j < 16; j++) acc[j] = 0.f;

    #pragma unroll
    for (int h = 0; h < 8; h++) {
        #pragma unroll
        for (int k = 0; k < 4; k++) {
            const float4 q = s_q[h * 128 + lane + 32 * k];
            acc[h]     += ra[k].x * q.x + ra[k].y * q.y + ra[k].z * q.z + ra[k].w * q.w;
            acc[8 + h] += rb[k].x * q.x + rb[k].y * q.y + rb[k].z * q.z + rb[k].w * q.w;
        }
    }
    #pragma unroll
    for (int j = 0; j < 16; j++) {
        float v = acc[j];
        #pragma unroll
        for (int o = 16; o; o >>= 1) v += __shfl_xor_sync(0xffffffffu, v, o);
        acc[j] = v;
    }
    if (lane == 0) {
        #pragma unroll
        for (int j = 0; j < 16; j++) {
            const int r = j >> 3, h = j & 7;
            const int row = row0 + r;
            const int b = row / P, p = row - b * P;
            g_scores[(size_t)b * (P * H) + p * H + h] = acc[j];
        }
    }
}

// ---------------------------------------------------------------------------
// K2: softmax over p + weighted pooling. Block per (b, d-half). Unchanged.
// ---------------------------------------------------------------------------
__global__ __launch_bounds__(256) void k_softmax_pool(
    const float* __restrict__ patch,
    float* __restrict__ out_semtok)
{
    __shared__ __align__(16) float s_w[P * H];   // 6.3 KB, layout [p][h]
    const int b  = blockIdx.x >> 1;
    const int dh = blockIdx.x & 1;
    const int tid = threadIdx.x;

    for (int i = tid; i < P * H; i += 256) s_w[i] = g_scores[(size_t)b * (P * H) + i];
    __syncthreads();

    const int w = tid >> 5, lane = tid & 31;     // warp w = head w
    {
        float m = -1e30f;
        for (int p = lane; p < P; p += 32) m = fmaxf(m, s_w[p * H + w]);
        #pragma unroll
        for (int o = 16; o; o >>= 1) m = fmaxf(m, __shfl_xor_sync(0xffffffffu, m, o));
        float s = 0.f;
        for (int p = lane; p < P; p += 32) s += __expf(s_w[p * H + w] - m);
        #pragma unroll
        for (int o = 16; o; o >>= 1) s += __shfl_xor_sync(0xffffffffu, s, o);
        const float inv = 1.0f / s;
        for (int p = lane; p < P; p += 32)
            s_w[p * H + w] = __expf(s_w[p * H + w] - m) * inv;
    }
    __syncthreads();

    const int d = dh * 256 + tid;
    const float* pb = patch + (size_t)b * P * D + d;
    float acc[8];
    #pragma unroll
    for (int h = 0; h < 8; h++) acc[h] = 0.f;

    #pragma unroll 4
    for (int p = 0; p < P; p++) {
        const float x = pb[(size_t)p * D];
        const float4 w0 = *(const float4*)&s_w[p * H];
        const float4 w1 = *(const float4*)&s_w[p * H + 4];
        acc[0] += w0.x * x; acc[1] += w0.y * x; acc[2] += w0.z * x; acc[3] += w0.w * x;
        acc[4] += w1.x * x; acc[5] += w1.y * x; acc[6] += w1.z * x; acc[7] += w1.w * x;
    }
    #pragma unroll
    for (int h = 0; h < 8; h++) {
        const size_t o = ((size_t)b * H + h) * D + d;
        g_semtok[o] = acc[h];
        out_semtok[o] = acc[h];
    }
}

// ---------------------------------------------------------------------------
// K3: projected_sem. OCCUPANCY-FIRST redesign: grid 256 = (h:8, et:16, bh:2),
// 512 thr = 32 e x 16 b. Thread owns ONE (b,e) dot: 1 LDS.128 + 1 LDG.128
// per iter (was 4 LDS + 1 LDG on 64 blocks -> crossbar+latency bound).
// ---------------------------------------------------------------------------
constexpr int PS_STRIDE = 516;  // floats; 516%32=4 -> LDS.128 phases conflict-free

__global__ __launch_bounds__(512) void k_psem(
    const float* __restrict__ semW,   // (H,D,D)
    const float* __restrict__ semb)   // (H,D)
{
    __shared__ float s_t[16 * PS_STRIDE];   // 33 KB
    const int bid = blockIdx.x;
    const int h  = bid >> 5;
    const int et = (bid >> 1) & 15;
    const int bh = bid & 1;
    const int tid = threadIdx.x;
    const int b0 = bh * 16;

    for (int i = tid; i < 16 * (D / 4); i += 512) {
        const int bb = i >> 7, col = i & 127;
        const float4 v = *(const float4*)&g_semtok[((size_t)(b0 + bb) * H + h) * D + col * 4];
        *(float4*)&s_t[bb * PS_STRIDE + col * 4] = v;
    }
    __syncthreads();

    const int e  = et * 32 + (tid >> 4);   // 16 consecutive threads share e (L1 bcast)
    const int bq = tid & 15;
    const float4* wrow = (const float4*)(semW + ((size_t)h * D + e) * D);
    const float* xs = &s_t[bq * PS_STRIDE];

    float a0 = 0.f, a1 = 0.f;
    #pragma unroll 8
    for (int i = 0; i < 128; i += 2) {     // 2 accumulators, 8-deep MLP
        const float4 w4 = wrow[i];
        const float4 x4 = *(const float4*)&xs[i * 4];
        const float4 w5 = wrow[i + 1];
        const float4 x5 = *(const float4*)&xs[(i + 1) * 4];
        a0 += w4.x * x4.x + w4.y * x4.y + w4.z * x4.z + w4.w * x4.w;
        a1 += w5.x * x5.x + w5.y * x5.y + w5.z * x5.z + w5.w * x5.w;
    }
    g_psem[((size_t)(b0 + bq) * H + h) * D + e] = a0 + a1 + semb[(size_t)h * D + e];
}

// ---------------------------------------------------------------------------
// K4: projected_domain + unknown_prompts. Same redesign: grid 32 = (et:16,
// bh:2), 512 thr = 32 e x 16 b. Broadcast rows partitioned by (b-half, e-slice).
// ---------------------------------------------------------------------------
__global__ __launch_bounds__(512) void k_pdom_unknown(
    const float* __restrict__ gf,     // (B,D)
    const float* __restrict__ Wm,     // (D,D)
    const float* __restrict__ bv,     // (D,)
    const float* __restrict__ upre,   // (1,D)
    const float* __restrict__ usem,   // (U,D)
    const float* __restrict__ usuf,   // (1,D)
    float* __restrict__ out_unknown)  // (B, U+3, D)
{
    __shared__ float s_g[16 * PS_STRIDE];
    const int bid = blockIdx.x;       // 0..31
    const int et = bid >> 1;
    const int bh = bid & 1;
    const int tid = threadIdx.x;
    const int b0 = bh * 16;

    for (int i = tid; i < 16 * (D / 4); i += 512) {
        const int bb = i >> 7, col = i & 127;
        const float4 v = *(const float4*)&gf[(size_t)(b0 + bb) * D + col * 4];
        *(float4*)&s_g[bb * PS_STRIDE + col * 4] = v;
    }
    __syncthreads();

    const int e  = et * 32 + (tid >> 4);
    const int bq = tid & 15;
    const int b  = b0 + bq;
    const float4* wrow = (const float4*)(Wm + (size_t)e * D);
    const float* xs = &s_g[bq * PS_STRIDE];

    float a0 = 0.f, a1 = 0.f;
    #pragma unroll 8
    for (int i = 0; i < 128; i += 2) {
        const float4 w4 = wrow[i];
        const float4 x4 = *(const float4*)&xs[i * 4];
        const float4 w5 = wrow[i + 1];
        const float4 x5 = *(const float4*)&xs[(i + 1) * 4];
        a0 += w4.x * x4.x + w4.y * x4.y + w4.z * x4.z + w4.w * x4.w;
        a1 += w5.x * x5.x + w5.y * x5.y + w5.z * x5.z + w5.w * x5.w;
    }
    const float val = a0 + a1 + bv[e];
    g_pdom[(size_t)b * D + e] = val;
    out_unknown[(size_t)b * ((U + 3) * D) + D + e] = val;   // row 1 = dom

    // broadcast rows: this block covers its 16 b's x 6 rows x its 32-e slice
    for (int i = tid; i < 16 * 6 * 32; i += 512) {
        const int bb = i / (6 * 32);
        const int rem = i - bb * (6 * 32);
        const int rr = rem >> 5;          // 0..5
        const int dd = et * 32 + (rem & 31);
        int brow; float v;
        if (rr == 0)      { brow = 0;       v = upre[dd]; }
        else if (rr <= 4) { brow = 1 + rr;  v = usem[(size_t)(rr - 1) * D + dd]; }
        else              { brow = U + 2;   v = usuf[dd]; }
        out_unknown[(size_t)(b0 + bb) * ((U + 3) * D) + (size_t)brow * D + dd] = v;
    }
}

// ---------------------------------------------------------------------------
// K5: known_prompts via smem staging + one 45KB cp.async.bulk S2G per block.
// MEASURED: 54.7us @ 5534 GB/s (69.8% DRAM). Frozen.
// ---------------------------------------------------------------------------
constexpr int PPB        = 2;
constexpr int ROW_F4     = D / 4;                // 128
constexpr int PROMPT_ROWS = H + 3;               // 11
constexpr int PROMPT_F4  = PROMPT_ROWS * ROW_F4; // 1408
constexpr int BLK_F4     = PPB * PROMPT_F4;      // 2816
constexpr unsigned BLK_BYTES = BLK_F4 * 16u;     // 45056

__global__ __launch_bounds__(256) void k_known(
    const float* __restrict__ pre,    // (C,1,D)
    const float* __restrict__ suf,    // (C,1,D)
    float* __restrict__ out)
{
    __shared__ __align__(128) float4 s_buf[BLK_F4];

    const int pair0 = blockIdx.x * PPB;
    const int b = pair0 / C;
    const int c0 = pair0 - b * C;
    const int t = threadIdx.x;

    const float4* f_pre = (const float4*)pre;
    const float4* f_suf = (const float4*)suf;
    const float4* f_dom = (const float4*)(g_pdom + (size_t)b * D);
    const float4* f_sem = (const float4*)(g_psem + (size_t)b * H * D);

    #pragma unroll
    for (int k = 0; k < BLK_F4 / 256; k++) {
        const int idx = t + k * 256;
        const int v   = idx & (ROW_F4 - 1);
        const int row = idx >> 7;
        const int j   = row / PROMPT_ROWS;
        const int r   = row - j * PROMPT_ROWS;
        const int c   = c0 + j;
        float4 val;
        if (r == 0)                    val = f_pre[c * ROW_F4 + v];
        else if (r == 1)               val = f_dom[v];
        else if (r == PROMPT_ROWS - 1) val = f_suf[c * ROW_F4 + v];
        else                           val = f_sem[(r - 2) * ROW_F4 + v];
        s_buf[idx] = val;
    }
    __syncthreads();

    if (t == 0) {
        asm volatile("fence.proxy.async.shared::cta;" ::: "memory");
        uint32_t saddr = (uint32_t)__cvta_generic_to_shared(s_buf);
        float* gdst = out + (size_t)pair0 * PROMPT_ROWS * D;
        unsigned nbytes = BLK_BYTES;
        asm volatile("cp.async.bulk.global.shared::cta.bulk_group [%0], [%1], %2;"
                     :: "l"(gdst), "r"(saddr), "r"(nbytes) : "memory");
        asm volatile("cp.async.bulk.commit_group;" ::: "memory");
        asm volatile("cp.async.bulk.wait_group 0;" ::: "memory");
    }
}

// ---------------------------------------------------------------------------
extern "C" void kernel_launch(void* const* d_in, const int* in_sizes, int n_in,
                              void* d_out, int out_size)
{
    const float* patch  = (const float*)d_in[0];
    const float* gfeat  = (const float*)d_in[1];
    const float* query  = (const float*)d_in[2];
    const float* dom_W  = (const float*)d_in[3];
    const float* dom_b  = (const float*)d_in[4];
    const float* sem_W  = (const float*)d_in[5];
    const float* sem_b  = (const float*)d_in[6];
    const float* usem   = (const float*)d_in[7];
    const float* kpre   = (const float*)d_in[8];
    const float* ksuf   = (const float*)d_in[9];
    const float* upre   = (const float*)d_in[10];
    const float* usuf   = (const float*)d_in[11];

    float* out = (float*)d_out;
    float* out_unknown = out + KNOWN_ELEMS;
    float* out_semtok  = out + KNOWN_ELEMS + UNK_ELEMS;

    k_scores<<<(B * P) / 16, 256>>>(patch, query);
    k_softmax_pool<<<B * 2, 256>>>(patch, out_semtok);
    k_psem<<<256, 512>>>(sem_W, sem_b);
    k_pdom_unknown<<<32, 512>>>(gfeat, dom_W, dom_b, upre, usem, usuf, out_unknown);
    k_known<<<(B * C) / PPB, 256>>>(kpre, ksuf, out);
}